// round 16
// baseline (speedup 1.0000x reference)
#include <cuda_runtime.h>

#define NB 2
#define NT 2048
#define NC 512
#define NH 16
#define ND 32
#define BT (NB*NT)          // 4096
#define SCALE 0.17677669529663687f          // 1/sqrt(32)
#define LOG2E 1.4426950408889634f
#define SCALE2 (SCALE * LOG2E)              // folded into Q at projection time
// Global band: no head has nonzero p beyond j=256.
#define KMAX 256
// Per-head band (exact fp32-underflow cutoffs, tile granularity 64):
__device__ __forceinline__ int kmax_h(int h) {
    return (h < 4) ? 128 : (h < 13) ? 192 : 256;
}

// Scratch (device globals), all tf32-rounded.
__device__ float g_q[NB*NH*NT*ND];
__device__ float g_k[NB*NH*NT*ND];
__device__ float g_v[NB*NH*NT*ND];
__device__ float g_o[NB*NH*NT*ND];
__device__ float g_ms[NB*NH*NT];
// tf32-rounded (RNA) copies of inputs — producer-side rounding (load-bearing:
// R11 proved truncation breaks the 1e-3 gate).
__device__ float g_xr[BT*NC];
__device__ float g_wr[4][NC*NC];

__device__ __forceinline__ unsigned f2tf(float f) {
    unsigned u; asm("cvt.rna.tf32.f32 %0, %1;" : "=r"(u) : "f"(f)); return u;
}
__device__ __forceinline__ float ex2f(float x) {
    float y; asm("ex2.approx.f32 %0, %1;" : "=f"(y) : "f"(x)); return y;
}
__device__ __forceinline__ float lg2f(float x) {
    float y; asm("lg2.approx.f32 %0, %1;" : "=f"(y) : "f"(x)); return y;
}

__device__ __forceinline__ void mma8(float d[4], const unsigned a[4], const unsigned b[2]) {
    asm("mma.sync.aligned.m16n8k8.row.col.f32.tf32.tf32.f32 "
        "{%0,%1,%2,%3},{%4,%5,%6,%7},{%8,%9},{%0,%1,%2,%3};"
        : "+f"(d[0]), "+f"(d[1]), "+f"(d[2]), "+f"(d[3])
        : "r"(a[0]), "r"(a[1]), "r"(a[2]), "r"(a[3]), "r"(b[0]), "r"(b[1]));
}

__device__ __forceinline__ void ldsm4(unsigned r[4], const void* p) {
    unsigned a = (unsigned)__cvta_generic_to_shared(p);
    asm volatile("ldmatrix.sync.aligned.m8n8.x4.shared.b16 {%0,%1,%2,%3}, [%4];"
        : "=r"(r[0]), "=r"(r[1]), "=r"(r[2]), "=r"(r[3]) : "r"(a));
}

__device__ __forceinline__ void cpa16(void* s, const void* g) {
    unsigned sa = (unsigned)__cvta_generic_to_shared(s);
    asm volatile("cp.async.cg.shared.global [%0], [%1], 16;" :: "r"(sa), "l"(g));
}
__device__ __forceinline__ void cpcommit() { asm volatile("cp.async.commit_group;"); }
template<int N> __device__ __forceinline__ void cpwait() {
    asm volatile("cp.async.wait_group %0;" :: "n"(N));
}

// ---------------------------------------------------------------------------
// Pre-round x and weights to tf32 (one float4 per thread).
// ---------------------------------------------------------------------------
__global__ __launch_bounds__(256) void pre_round(const float* __restrict__ x,
    const float* __restrict__ Wq, const float* __restrict__ Wk,
    const float* __restrict__ Wv, const float* __restrict__ Wo) {
    const int NX = BT * NC / 4;
    const int NW = NC * NC / 4;
    int idx = blockIdx.x * blockDim.x + threadIdx.x;
    float4 v; float* dst;
    if (idx < NX) {
        v = ((const float4*)x)[idx];
        dst = g_xr + (size_t)idx * 4;
    } else {
        int j = idx - NX;
        int w = j / NW, o = j - w * NW;
        const float* W = w == 0 ? Wq : (w == 1 ? Wk : (w == 2 ? Wv : Wo));
        v = ((const float4*)W)[o];
        dst = g_wr[w] + (size_t)o * 4;
    }
    float4 r;
    r.x = __uint_as_float(f2tf(v.x)); r.y = __uint_as_float(f2tf(v.y));
    r.z = __uint_as_float(f2tf(v.z)); r.w = __uint_as_float(f2tf(v.w));
    *(float4*)dst = r;
}

// ---------------------------------------------------------------------------
// 2-stage tiles (small smem -> 3 CTAs/SM).
struct __align__(16) GemmSmem {
    float As[2][128][36];   // 36,864 B
    float Bs[2][64][36];    // 18,432 B -> 55,296 total
};
struct __align__(16) AvgSmem {
    unsigned Qs[2][64][36];
    unsigned Ks[2][64][36]; // 36,864 B
};

// ---------------------------------------------------------------------------
// QKV projection from pre-rounded g_xr/g_wr — no cvt in the mma loop.
// Q: full, scaled by SCALE2. K/V: tokens < KMAX. V stored transposed (B,H,D,T).
// The 448 banded-out K/V blocks zero-fill avg's out-of-band region (28MB)
// in the shadow of the compute-bound Q/K/V mma work.
// Grid (BT/128, NC/64, 3), 256 threads, 2-stage cp.async, 3 CTAs/SM.
// ---------------------------------------------------------------------------
__global__ __launch_bounds__(256,3) void gemm_qkv(
    const float* __restrict__ bq, const float* __restrict__ bk,
    const float* __restrict__ bv, float* __restrict__ avg) {
    int sel = blockIdx.z;
    int m0 = blockIdx.x * 128, n0 = blockIdx.y * 64;
    if (sel != 0 && (m0 & (NT - 1)) >= KMAX) {
        // ---- zero-fill avg[:, :, KMAX:NT] (exactly 0 for every head) ----
        // 448 such blocks; each writes 4096 float4 (16 per thread), coalesced.
        int xo = (blockIdx.x & 15) - 2;            // 0..13 within batch
        int bi = blockIdx.x >> 4;                  // 0..1
        int zid = (bi * 14 + xo) + 28 * (blockIdx.y + 8 * (sel - 1)); // 0..447
        const int F4_PER_ROW = (NT - KMAX) / 4;    // 448
        float4 z = make_float4(0.f, 0.f, 0.f, 0.f);
        int tid = threadIdx.x;
#pragma unroll
        for (int i = 0; i < 16; i++) {
            int f4 = zid * 4096 + i * 256 + tid;   // 448*4096 = 4096 rows * 448
            int row = f4 / F4_PER_ROW;             // b*NT + q
            int c4  = f4 - row * F4_PER_ROW;
            *(float4*)&avg[(size_t)row * NT + KMAX + c4 * 4] = z;
        }
        return;
    }

    extern __shared__ char smraw[];
    GemmSmem& sm = *reinterpret_cast<GemmSmem*>(smraw);
    const float* W    = g_wr[sel];
    const float* bias = sel == 0 ? bq : (sel == 1 ? bk : bv);
    float* outp       = sel == 0 ? g_q : (sel == 1 ? g_k : g_v);

    int tid = threadIdx.x, wid = tid >> 5, lane = tid & 31, g = lane >> 2, t = lane & 3;
    int wm = (wid & 3) * 32, wn = (wid >> 2) * 32;
    int lrow = lane & 15, lcol = 4 * (lane >> 4);

    {
#pragma unroll
        for (int i = 0; i < 4; i++) {
            int idx = tid + i * 256; int r = idx >> 3, c = (idx & 7) * 4;
            cpa16(&sm.As[0][r][c], &g_xr[(size_t)(m0 + r) * NC + c]);
        }
#pragma unroll
        for (int i = 0; i < 2; i++) {
            int idx = tid + i * 256; int r = idx >> 3, c = (idx & 7) * 4;
            cpa16(&sm.Bs[0][r][c], &W[(size_t)(n0 + r) * NC + c]);
        }
        cpcommit();
    }

    float acc[2][4][4] = {};
    int cb = 0;
    for (int k0 = 0; k0 < NC; k0 += 32, cb ^= 1) {
        __syncthreads();
        if (k0 + 32 < NC) {
            int kn = k0 + 32;
#pragma unroll
            for (int i = 0; i < 4; i++) {
                int idx = tid + i * 256; int r = idx >> 3, c = (idx & 7) * 4;
                cpa16(&sm.As[cb^1][r][c], &g_xr[(size_t)(m0 + r) * NC + kn + c]);
            }
#pragma unroll
            for (int i = 0; i < 2; i++) {
                int idx = tid + i * 256; int r = idx >> 3, c = (idx & 7) * 4;
                cpa16(&sm.Bs[cb^1][r][c], &W[(size_t)(n0 + r) * NC + kn + c]);
            }
            cpcommit(); cpwait<1>();
        } else cpwait<0>();
        __syncthreads();
#pragma unroll
        for (int kk = 0; kk < 32; kk += 8) {
            unsigned a[2][4];
            ldsm4(a[0], &sm.As[cb][wm + lrow][kk + lcol]);
            ldsm4(a[1], &sm.As[cb][wm + 16 + lrow][kk + lcol]);
#pragma unroll
            for (int nj = 0; nj < 4; nj += 2) {
                unsigned r[4];
                ldsm4(r, &sm.Bs[cb][wn + nj * 8 + lrow][kk + lcol]);
                unsigned b0[2] = { r[0], r[2] }, b1[2] = { r[1], r[3] };
                mma8(acc[0][nj], a[0], b0);  mma8(acc[0][nj+1], a[0], b1);
                mma8(acc[1][nj], a[1], b0);  mma8(acc[1][nj+1], a[1], b1);
            }
        }
    }
#pragma unroll
    for (int mi = 0; mi < 2; mi++) {
        int r0 = m0 + wm + mi * 16 + g;
        int r1 = r0 + 8;
        int b0i = r0 >> 11, t0 = r0 & 2047;
        int b1i = r1 >> 11, t1 = r1 & 2047;
#pragma unroll
        for (int ni = 0; ni < 4; ni++) {
            int n = n0 + wn + ni * 8 + 2 * t;
            int h = n >> 5, d = n & 31;
            float bb0 = bias[n], bb1 = bias[n + 1];
            float v00 = acc[mi][ni][0] + bb0, v01 = acc[mi][ni][1] + bb1;
            float v10 = acc[mi][ni][2] + bb0, v11 = acc[mi][ni][3] + bb1;
            if (sel == 2) {
                size_t vb0 = ((size_t)(b0i * NH + h) * ND + d) * NT + t0;
                size_t vb1 = ((size_t)(b1i * NH + h) * ND + d) * NT + t1;
                outp[vb0]      = __uint_as_float(f2tf(v00));
                outp[vb0 + NT] = __uint_as_float(f2tf(v01));
                outp[vb1]      = __uint_as_float(f2tf(v10));
                outp[vb1 + NT] = __uint_as_float(f2tf(v11));
            } else {
                if (sel == 0) { v00 *= SCALE2; v01 *= SCALE2; v10 *= SCALE2; v11 *= SCALE2; }
                size_t base0 = ((size_t)(b0i * NH + h) * NT + t0) * ND;
                size_t base1 = ((size_t)(b1i * NH + h) * NT + t1) * ND;
                *(float2*)&outp[base0 + d] = make_float2(__uint_as_float(f2tf(v00)),
                                                         __uint_as_float(f2tf(v01)));
                *(float2*)&outp[base1 + d] = make_float2(__uint_as_float(f2tf(v10)),
                                                         __uint_as_float(f2tf(v11)));
            }
        }
    }
}

// ---------------------------------------------------------------------------
// Flash attention, static shift, per-head band [0, kmax_h). 2-stage.
// Grid (NT/128, NH, NB), 256 threads, dynamic smem (89,088 B, 2 CTAs/SM).
// ---------------------------------------------------------------------------
struct __align__(16) FlashSmem {
    unsigned Qs[128][36];
    unsigned Ks[2][64][36];
    unsigned Vt[2][32][68];
    unsigned Ps[128][68];
};

__global__ __launch_bounds__(256,2) void flash_attn() {
    extern __shared__ char smraw[];
    FlashSmem& sm = *reinterpret_cast<FlashSmem*>(smraw);
    int q0 = blockIdx.x * 128, h = blockIdx.y, b = blockIdx.z;
    int bh = b * NH + h;
    int kmaxh = kmax_h(h);
    int tid = threadIdx.x, wid = tid >> 5, lane = tid & 31, g = lane >> 2, t = lane & 3;
    int wm = wid * 16;
    int lrow = lane & 15, lcol = 4 * (lane >> 4);
    const float* qp = g_q + (size_t)bh * NT * ND;
    const float* kp = g_k + (size_t)bh * NT * ND;
    const float* vp = g_v + (size_t)bh * ND * NT;

#pragma unroll
    for (int i = 0; i < 4; i++) {
        int idx = tid + i * 256; int r = idx >> 3, c = (idx & 7) * 4;
        cpa16(&sm.Qs[r][c], &qp[(size_t)(q0 + r) * ND + c]);
    }
#pragma unroll
    for (int i = 0; i < 2; i++) {
        int idx = tid + i * 256;
        { int r = idx >> 3, c = (idx & 7) * 4;
          cpa16(&sm.Ks[0][r][c], &kp[(size_t)r * ND + c]); }
        { int r = idx >> 4, c = (idx & 15) * 4;
          cpa16(&sm.Vt[0][r][c], &vp[(size_t)r * NT + c]); }
    }
    cpcommit();

    float slope2 = exp2f(-(float)(h + 1) * (1.0f / 16.0f)) * LOG2E;
    float l0 = 0.f, l1 = 0.f;
    float oacc[4][4] = {};
    int qi0 = q0 + wm + g, qi1 = qi0 + 8;
    float skc[8];
#pragma unroll
    for (int ni = 0; ni < 8; ni++) skc[ni] = slope2 * (float)(ni * 8 + 2 * t);
    int cb = 0;

    for (int kt = 0; kt < kmaxh; kt += 64, cb ^= 1) {
        __syncthreads();
        if (kt + 64 < kmaxh) {
            const float* kp2 = kp + (size_t)(kt + 64) * ND;
            const float* vp2 = vp + (kt + 64);
#pragma unroll
            for (int i = 0; i < 2; i++) {
                int idx = tid + i * 256;
                { int r = idx >> 3, c = (idx & 7) * 4;
                  cpa16(&sm.Ks[cb^1][r][c], &kp2[(size_t)r * ND + c]); }
                { int r = idx >> 4, c = (idx & 15) * 4;
                  cpa16(&sm.Vt[cb^1][r][c], &vp2[(size_t)r * NT + c]); }
            }
            cpcommit(); cpwait<1>();
        } else cpwait<0>();
        __syncthreads();

        float sacc[8][4] = {};
#pragma unroll
        for (int kk = 0; kk < 32; kk += 8) {
            unsigned a[4];
            ldsm4(a, &sm.Qs[wm + lrow][kk + lcol]);
#pragma unroll
            for (int nj = 0; nj < 8; nj += 2) {
                unsigned r[4];
                ldsm4(r, &sm.Ks[cb][nj * 8 + lrow][kk + lcol]);
                unsigned b0[2] = { r[0], r[2] }, b1[2] = { r[1], r[3] };
                mma8(sacc[nj], a, b0); mma8(sacc[nj+1], a, b1);
            }
        }
        float base = -slope2 * (float)kt;
#pragma unroll
        for (int ni = 0; ni < 8; ni++) {
            float c0 = base - skc[ni];
            float c1 = c0 - slope2;
            float p0 = ex2f(sacc[ni][0] + c0);
            float p1 = ex2f(sacc[ni][1] + c1);
            float p2 = ex2f(sacc[ni][2] + c0);
            float p3 = ex2f(sacc[ni][3] + c1);
            l0 += p0 + p1; l1 += p2 + p3;
            int col = ni * 8 + 2 * t;
            *(uint2*)&sm.Ps[wm + g][col]     = make_uint2(f2tf(p0), f2tf(p1));
            *(uint2*)&sm.Ps[wm + g + 8][col] = make_uint2(f2tf(p2), f2tf(p3));
        }
        __syncwarp();
#pragma unroll
        for (int kk = 0; kk < 64; kk += 8) {
            unsigned a[4];
            ldsm4(a, &sm.Ps[wm + lrow][kk + lcol]);
#pragma unroll
            for (int nj = 0; nj < 4; nj += 2) {
                unsigned r[4];
                ldsm4(r, &sm.Vt[cb][nj * 8 + lrow][kk + lcol]);
                unsigned b0[2] = { r[0], r[2] }, b1[2] = { r[1], r[3] };
                mma8(oacc[nj], a, b0); mma8(oacc[nj+1], a, b1);
            }
        }
    }
    l0 += __shfl_xor_sync(~0u, l0, 1); l0 += __shfl_xor_sync(~0u, l0, 2);
    l1 += __shfl_xor_sync(~0u, l1, 1); l1 += __shfl_xor_sync(~0u, l1, 2);
    float il0 = __fdividef(1.f, l0), il1 = __fdividef(1.f, l1);
#pragma unroll
    for (int ni = 0; ni < 4; ni++) {
        int col = ni * 8 + 2 * t;
        *(float2*)&g_o[((size_t)bh * NT + qi0) * ND + col] =
            make_float2(__uint_as_float(f2tf(oacc[ni][0] * il0)),
                        __uint_as_float(f2tf(oacc[ni][1] * il0)));
        *(float2*)&g_o[((size_t)bh * NT + qi1) * ND + col] =
            make_float2(__uint_as_float(f2tf(oacc[ni][2] * il1)),
                        __uint_as_float(f2tf(oacc[ni][3] * il1)));
    }
    if (t == 0) {
        g_ms[(size_t)bh * NT + qi0] = lg2f(l0);
        g_ms[(size_t)bh * NT + qi1] = lg2f(l1);
    }
}

// ---------------------------------------------------------------------------
// Fused tail: avg_probs in-band (z = 0,1) + gemm_out (z = 2, y < 8).
// Out-of-band avg was zero-filled by gemm_qkv's idle blocks.
// Grid (32, 32, 3), 256 threads, dynamic smem (55,296 B), 3 CTAs/SM.
// ---------------------------------------------------------------------------
__global__ __launch_bounds__(256,3) void fused_tail(const float* __restrict__ bo,
                                                    float* __restrict__ out,
                                                    float* __restrict__ avg) {
    extern __shared__ char smraw[];
    int tid = threadIdx.x;

    if (blockIdx.z == 2) {
        // ---------------- gemm_out ----------------
        if (blockIdx.y >= 8) return;
        GemmSmem& sm = *reinterpret_cast<GemmSmem*>(smraw);
        const float* Wo = g_wr[3];
        int m0 = blockIdx.x * 128, n0 = blockIdx.y * 64;
        int wid = tid >> 5, lane = tid & 31, g = lane >> 2, t = lane & 3;
        int wm = (wid & 3) * 32, wn = (wid >> 2) * 32;
        int lrow = lane & 15, lcol = 4 * (lane >> 4);

        {
#pragma unroll
            for (int i = 0; i < 4; i++) {
                int idx = tid + i * 256; int r = idx >> 3, c = (idx & 7) * 4;
                int m = m0 + r; int bi = m >> 11, tt = m & 2047;
                cpa16(&sm.As[0][r][c], &g_o[((size_t)(bi * NH) * NT + tt) * ND + c]);
            }
#pragma unroll
            for (int i = 0; i < 2; i++) {
                int idx = tid + i * 256; int r = idx >> 3, c = (idx & 7) * 4;
                cpa16(&sm.Bs[0][r][c], &Wo[(size_t)(n0 + r) * NC + c]);
            }
            cpcommit();
        }

        float acc[2][4][4] = {};
        int cb = 0;
        for (int k0 = 0; k0 < NC; k0 += 32, cb ^= 1) {
            __syncthreads();
            if (k0 + 32 < NC) {
                int kn = k0 + 32;
                int hh = kn >> 5;
#pragma unroll
                for (int i = 0; i < 4; i++) {
                    int idx = tid + i * 256; int r = idx >> 3, c = (idx & 7) * 4;
                    int m = m0 + r; int bi = m >> 11, tt = m & 2047;
                    cpa16(&sm.As[cb^1][r][c], &g_o[((size_t)(bi * NH + hh) * NT + tt) * ND + c]);
                }
#pragma unroll
                for (int i = 0; i < 2; i++) {
                    int idx = tid + i * 256; int r = idx >> 3, c = (idx & 7) * 4;
                    cpa16(&sm.Bs[cb^1][r][c], &Wo[(size_t)(n0 + r) * NC + kn + c]);
                }
                cpcommit(); cpwait<1>();
            } else cpwait<0>();
            __syncthreads();
#pragma unroll
            for (int kk = 0; kk < 32; kk += 8) {
                unsigned a[2][4];
                ldsm4(a[0], &sm.As[cb][wm + lrow][kk + lcol]);
                ldsm4(a[1], &sm.As[cb][wm + 16 + lrow][kk + lcol]);
#pragma unroll
                for (int nj = 0; nj < 4; nj += 2) {
                    unsigned r[4];
                    ldsm4(r, &sm.Bs[cb][wn + nj * 8 + lrow][kk + lcol]);
                    unsigned b0[2] = { r[0], r[2] }, b1[2] = { r[1], r[3] };
                    mma8(acc[0][nj], a[0], b0);  mma8(acc[0][nj+1], a[0], b1);
                    mma8(acc[1][nj], a[1], b0);  mma8(acc[1][nj+1], a[1], b1);
                }
            }
        }
#pragma unroll
        for (int mi = 0; mi < 2; mi++) {
            int r0 = m0 + wm + mi * 16 + g;
            int r1 = r0 + 8;
#pragma unroll
            for (int ni = 0; ni < 4; ni++) {
                int n = n0 + wn + ni * 8 + 2 * t;
                float bb0 = bo[n], bb1 = bo[n + 1];
                *(float2*)&out[(size_t)r0 * NC + n] = make_float2(acc[mi][ni][0] + bb0, acc[mi][ni][1] + bb1);
                *(float2*)&out[(size_t)r1 * NC + n] = make_float2(acc[mi][ni][2] + bb0, acc[mi][ni][3] + bb1);
            }
        }
        return;
    }

    // ---------------- avg_probs (in-band only) ----------------
    int k0 = blockIdx.x * 64, q0 = blockIdx.y * 64, b = blockIdx.z;
    if (k0 >= KMAX) return;     // zero region already written by gemm_qkv

    // first head whose band covers this k-tile (earlier heads give exact 0)
    int h0 = (k0 >= 192) ? 13 : (k0 >= 128) ? 4 : 0;

    AvgSmem& sma = *reinterpret_cast<AvgSmem*>(smraw);
    int wid = tid >> 5, lane = tid & 31, g = lane >> 2, t = lane & 3;
    int wm = (wid >> 1) * 16, wn = (wid & 1) * 32;
    int lrow = lane & 15, lcol = 4 * (lane >> 4);
    int qi0 = q0 + wm + g, qi1 = qi0 + 8;
    float kj0f = (float)(k0 + wn + 2 * t);

    {
        int bh = b * NH + h0;
#pragma unroll
        for (int i = 0; i < 2; i++) {
            int idx = tid + i * 256; int r = idx >> 3, c = (idx & 7) * 4;
            cpa16(&sma.Qs[0][r][c], &g_q[((size_t)bh * NT + q0 + r) * ND + c]);
            cpa16(&sma.Ks[0][r][c], &g_k[((size_t)bh * NT + k0 + r) * ND + c]);
        }
        cpcommit();
    }
    float acc[4][4] = {};
    int cb = 0;
    for (int h = h0; h < NH; h++, cb ^= 1) {
        int bh = b * NH + h;
        __syncthreads();
        if (h + 1 < NH) {
            int bh2 = bh + 1;
#pragma unroll
            for (int i = 0; i < 2; i++) {
                int idx = tid + i * 256; int r = idx >> 3, c = (idx & 7) * 4;
                cpa16(&sma.Qs[cb^1][r][c], &g_q[((size_t)bh2 * NT + q0 + r) * ND + c]);
                cpa16(&sma.Ks[cb^1][r][c], &g_k[((size_t)bh2 * NT + k0 + r) * ND + c]);
            }
            cpcommit(); cpwait<1>();
        } else cpwait<0>();
        __syncthreads();

        float sacc[4][4] = {};
#pragma unroll
        for (int kk = 0; kk < 32; kk += 8) {
            unsigned a[4];
            ldsm4(a, &sma.Qs[cb][wm + lrow][kk + lcol]);
#pragma unroll
            for (int nj = 0; nj < 4; nj += 2) {
                unsigned r[4];
                ldsm4(r, &sma.Ks[cb][wn + nj * 8 + lrow][kk + lcol]);
                unsigned b0[2] = { r[0], r[2] }, b1[2] = { r[1], r[3] };
                mma8(sacc[nj], a, b0); mma8(sacc[nj+1], a, b1);
            }
        }
        float M0 = g_ms[(size_t)bh * NT + qi0];
        float M1 = g_ms[(size_t)bh * NT + qi1];
        float slope2 = exp2f(-(float)(h + 1) * (1.0f / 16.0f)) * LOG2E;
        float c0 = fmaf(-slope2, kj0f, -M0);
        float c1 = fmaf(-slope2, kj0f, -M1);
#pragma unroll
        for (int ni = 0; ni < 4; ni++) {
            float d0 = c0 - slope2 * (float)(ni * 8);
            float d1 = c1 - slope2 * (float)(ni * 8);
            acc[ni][0] += ex2f(sacc[ni][0] + d0);
            acc[ni][1] += ex2f(sacc[ni][1] + d0 - slope2);
            acc[ni][2] += ex2f(sacc[ni][2] + d1);
            acc[ni][3] += ex2f(sacc[ni][3] + d1 - slope2);
        }
    }
#pragma unroll
    for (int ni = 0; ni < 4; ni++) {
        int col = k0 + wn + ni * 8 + 2 * t;
        *(float2*)&avg[((size_t)b * NT + qi0) * NT + col] =
            make_float2(acc[ni][0] * 0.0625f, acc[ni][1] * 0.0625f);
        *(float2*)&avg[((size_t)b * NT + qi1) * NT + col] =
            make_float2(acc[ni][2] * 0.0625f, acc[ni][3] * 0.0625f);
    }
}

// ---------------------------------------------------------------------------
extern "C" void kernel_launch(void* const* d_in, const int* in_sizes, int n_in,
                              void* d_out, int out_size) {
    const float* x  = (const float*)d_in[0];
    const float* Wq = (const float*)d_in[1];
    const float* bq = (const float*)d_in[2];
    const float* Wk = (const float*)d_in[3];
    const float* bk = (const float*)d_in[4];
    const float* Wv = (const float*)d_in[5];
    const float* bv = (const float*)d_in[6];
    const float* Wo = (const float*)d_in[7];
    const float* bo = (const float*)d_in[8];

    float* out = (float*)d_out;                 // (B,T,C)
    float* avg = out + (size_t)NB*NT*NC;        // (B,T,T)

    cudaFuncSetAttribute(gemm_qkv, cudaFuncAttributeMaxDynamicSharedMemorySize,
                         (int)sizeof(GemmSmem));
    cudaFuncSetAttribute(flash_attn, cudaFuncAttributeMaxDynamicSharedMemorySize,
                         (int)sizeof(FlashSmem));
    cudaFuncSetAttribute(fused_tail, cudaFuncAttributeMaxDynamicSharedMemorySize,
                         (int)sizeof(GemmSmem));

    int npre = (BT * NC / 4 + 4 * NC * NC / 4) / 256;
    pre_round<<<npre, 256>>>(x, Wq, Wk, Wv, Wo);

    dim3 g1(BT/128, NC/64, 3);
    gemm_qkv<<<g1, 256, sizeof(GemmSmem)>>>(bq, bk, bv, avg);

    dim3 g2(NT/128, NH, NB);
    flash_attn<<<g2, 256, sizeof(FlashSmem)>>>();

    dim3 g3(NT/64, NT/64, 3);
    fused_tail<<<g3, 256, sizeof(GemmSmem)>>>(bo, out, avg);
}

// round 17
// speedup vs baseline: 1.0430x; 1.0430x over previous
#include <cuda_runtime.h>

#define NB 2
#define NT 2048
#define NC 512
#define NH 16
#define ND 32
#define BT (NB*NT)          // 4096
#define SCALE 0.17677669529663687f          // 1/sqrt(32)
#define LOG2E 1.4426950408889634f
#define SCALE2 (SCALE * LOG2E)              // folded into Q at projection time
// Global band: no head has nonzero p beyond j=256.
#define KMAX 256
// Per-head band (exact fp32-underflow cutoffs, tile granularity 64):
__device__ __forceinline__ int kmax_h(int h) {
    return (h < 4) ? 128 : (h < 13) ? 192 : 256;
}

// Scratch (device globals), all tf32-rounded.
__device__ float g_q[NB*NH*NT*ND];
__device__ float g_k[NB*NH*NT*ND];
__device__ float g_v[NB*NH*NT*ND];
__device__ float g_o[NB*NH*NT*ND];
__device__ float g_ms[NB*NH*NT];
// tf32-rounded (RNA) copies of inputs — producer-side rounding (load-bearing:
// R11 proved truncation breaks the 1e-3 gate).
__device__ float g_xr[BT*NC];
__device__ float g_wr[4][NC*NC];

__device__ __forceinline__ unsigned f2tf(float f) {
    unsigned u; asm("cvt.rna.tf32.f32 %0, %1;" : "=r"(u) : "f"(f)); return u;
}
__device__ __forceinline__ float ex2f(float x) {
    float y; asm("ex2.approx.f32 %0, %1;" : "=f"(y) : "f"(x)); return y;
}
__device__ __forceinline__ float lg2f(float x) {
    float y; asm("lg2.approx.f32 %0, %1;" : "=f"(y) : "f"(x)); return y;
}

__device__ __forceinline__ void mma8(float d[4], const unsigned a[4], const unsigned b[2]) {
    asm("mma.sync.aligned.m16n8k8.row.col.f32.tf32.tf32.f32 "
        "{%0,%1,%2,%3},{%4,%5,%6,%7},{%8,%9},{%0,%1,%2,%3};"
        : "+f"(d[0]), "+f"(d[1]), "+f"(d[2]), "+f"(d[3])
        : "r"(a[0]), "r"(a[1]), "r"(a[2]), "r"(a[3]), "r"(b[0]), "r"(b[1]));
}

__device__ __forceinline__ void ldsm4(unsigned r[4], const void* p) {
    unsigned a = (unsigned)__cvta_generic_to_shared(p);
    asm volatile("ldmatrix.sync.aligned.m8n8.x4.shared.b16 {%0,%1,%2,%3}, [%4];"
        : "=r"(r[0]), "=r"(r[1]), "=r"(r[2]), "=r"(r[3]) : "r"(a));
}

__device__ __forceinline__ void cpa16(void* s, const void* g) {
    unsigned sa = (unsigned)__cvta_generic_to_shared(s);
    asm volatile("cp.async.cg.shared.global [%0], [%1], 16;" :: "r"(sa), "l"(g));
}
__device__ __forceinline__ void cpcommit() { asm volatile("cp.async.commit_group;"); }
template<int N> __device__ __forceinline__ void cpwait() {
    asm volatile("cp.async.wait_group %0;" :: "n"(N));
}

// ---------------------------------------------------------------------------
// Pre-round x and weights to tf32 (one float4 per thread).
// ---------------------------------------------------------------------------
__global__ __launch_bounds__(256) void pre_round(const float* __restrict__ x,
    const float* __restrict__ Wq, const float* __restrict__ Wk,
    const float* __restrict__ Wv, const float* __restrict__ Wo) {
    const int NX = BT * NC / 4;
    const int NW = NC * NC / 4;
    int idx = blockIdx.x * blockDim.x + threadIdx.x;
    float4 v; float* dst;
    if (idx < NX) {
        v = ((const float4*)x)[idx];
        dst = g_xr + (size_t)idx * 4;
    } else {
        int j = idx - NX;
        int w = j / NW, o = j - w * NW;
        const float* W = w == 0 ? Wq : (w == 1 ? Wk : (w == 2 ? Wv : Wo));
        v = ((const float4*)W)[o];
        dst = g_wr[w] + (size_t)o * 4;
    }
    float4 r;
    r.x = __uint_as_float(f2tf(v.x)); r.y = __uint_as_float(f2tf(v.y));
    r.z = __uint_as_float(f2tf(v.z)); r.w = __uint_as_float(f2tf(v.w));
    *(float4*)dst = r;
}

// ---------------------------------------------------------------------------
// 2-stage tiles (small smem -> 3 CTAs/SM).
struct __align__(16) GemmSmem {
    float As[2][128][36];   // 36,864 B
    float Bs[2][64][36];    // 18,432 B -> 55,296 total
};
struct __align__(16) AvgSmem {
    unsigned Qs[2][64][36];
    unsigned Ks[2][64][36]; // 36,864 B
};

// ---------------------------------------------------------------------------
// QKV projection from pre-rounded g_xr/g_wr — no cvt in the mma loop.
// Q: full, scaled by SCALE2. K/V: tokens < KMAX. V stored transposed (B,H,D,T).
// The 448 banded-out K/V blocks zero-fill avg's out-of-band region (28MB).
// Grid (BT/128, NC/64, 3), 256 threads, 2-stage cp.async, 3 CTAs/SM.
// ---------------------------------------------------------------------------
__global__ __launch_bounds__(256,3) void gemm_qkv(
    const float* __restrict__ bq, const float* __restrict__ bk,
    const float* __restrict__ bv, float* __restrict__ avg) {
    int sel = blockIdx.z;
    int m0 = blockIdx.x * 128, n0 = blockIdx.y * 64;
    if (sel != 0 && (m0 & (NT - 1)) >= KMAX) {
        // ---- zero-fill avg[:, :, KMAX:NT] (exactly 0 for every head) ----
        int xo = (blockIdx.x & 15) - 2;            // 0..13 within batch
        int bi = blockIdx.x >> 4;                  // 0..1
        int zid = (bi * 14 + xo) + 28 * (blockIdx.y + 8 * (sel - 1)); // 0..447
        const int F4_PER_ROW = (NT - KMAX) / 4;    // 448
        float4 z = make_float4(0.f, 0.f, 0.f, 0.f);
        int tid = threadIdx.x;
#pragma unroll
        for (int i = 0; i < 16; i++) {
            int f4 = zid * 4096 + i * 256 + tid;
            int row = f4 / F4_PER_ROW;             // b*NT + q
            int c4  = f4 - row * F4_PER_ROW;
            *(float4*)&avg[(size_t)row * NT + KMAX + c4 * 4] = z;
        }
        return;
    }

    extern __shared__ char smraw[];
    GemmSmem& sm = *reinterpret_cast<GemmSmem*>(smraw);
    const float* W    = g_wr[sel];
    const float* bias = sel == 0 ? bq : (sel == 1 ? bk : bv);
    float* outp       = sel == 0 ? g_q : (sel == 1 ? g_k : g_v);

    int tid = threadIdx.x, wid = tid >> 5, lane = tid & 31, g = lane >> 2, t = lane & 3;
    int wm = (wid & 3) * 32, wn = (wid >> 2) * 32;
    int lrow = lane & 15, lcol = 4 * (lane >> 4);

    {
#pragma unroll
        for (int i = 0; i < 4; i++) {
            int idx = tid + i * 256; int r = idx >> 3, c = (idx & 7) * 4;
            cpa16(&sm.As[0][r][c], &g_xr[(size_t)(m0 + r) * NC + c]);
        }
#pragma unroll
        for (int i = 0; i < 2; i++) {
            int idx = tid + i * 256; int r = idx >> 3, c = (idx & 7) * 4;
            cpa16(&sm.Bs[0][r][c], &W[(size_t)(n0 + r) * NC + c]);
        }
        cpcommit();
    }

    float acc[2][4][4] = {};
    int cb = 0;
    for (int k0 = 0; k0 < NC; k0 += 32, cb ^= 1) {
        __syncthreads();
        if (k0 + 32 < NC) {
            int kn = k0 + 32;
#pragma unroll
            for (int i = 0; i < 4; i++) {
                int idx = tid + i * 256; int r = idx >> 3, c = (idx & 7) * 4;
                cpa16(&sm.As[cb^1][r][c], &g_xr[(size_t)(m0 + r) * NC + kn + c]);
            }
#pragma unroll
            for (int i = 0; i < 2; i++) {
                int idx = tid + i * 256; int r = idx >> 3, c = (idx & 7) * 4;
                cpa16(&sm.Bs[cb^1][r][c], &W[(size_t)(n0 + r) * NC + kn + c]);
            }
            cpcommit(); cpwait<1>();
        } else cpwait<0>();
        __syncthreads();
#pragma unroll
        for (int kk = 0; kk < 32; kk += 8) {
            unsigned a[2][4];
            ldsm4(a[0], &sm.As[cb][wm + lrow][kk + lcol]);
            ldsm4(a[1], &sm.As[cb][wm + 16 + lrow][kk + lcol]);
#pragma unroll
            for (int nj = 0; nj < 4; nj += 2) {
                unsigned r[4];
                ldsm4(r, &sm.Bs[cb][wn + nj * 8 + lrow][kk + lcol]);
                unsigned b0[2] = { r[0], r[2] }, b1[2] = { r[1], r[3] };
                mma8(acc[0][nj], a[0], b0);  mma8(acc[0][nj+1], a[0], b1);
                mma8(acc[1][nj], a[1], b0);  mma8(acc[1][nj+1], a[1], b1);
            }
        }
    }
#pragma unroll
    for (int mi = 0; mi < 2; mi++) {
        int r0 = m0 + wm + mi * 16 + g;
        int r1 = r0 + 8;
        int b0i = r0 >> 11, t0 = r0 & 2047;
        int b1i = r1 >> 11, t1 = r1 & 2047;
#pragma unroll
        for (int ni = 0; ni < 4; ni++) {
            int n = n0 + wn + ni * 8 + 2 * t;
            int h = n >> 5, d = n & 31;
            float bb0 = bias[n], bb1 = bias[n + 1];
            float v00 = acc[mi][ni][0] + bb0, v01 = acc[mi][ni][1] + bb1;
            float v10 = acc[mi][ni][2] + bb0, v11 = acc[mi][ni][3] + bb1;
            if (sel == 2) {
                size_t vb0 = ((size_t)(b0i * NH + h) * ND + d) * NT + t0;
                size_t vb1 = ((size_t)(b1i * NH + h) * ND + d) * NT + t1;
                outp[vb0]      = __uint_as_float(f2tf(v00));
                outp[vb0 + NT] = __uint_as_float(f2tf(v01));
                outp[vb1]      = __uint_as_float(f2tf(v10));
                outp[vb1 + NT] = __uint_as_float(f2tf(v11));
            } else {
                if (sel == 0) { v00 *= SCALE2; v01 *= SCALE2; v10 *= SCALE2; v11 *= SCALE2; }
                size_t base0 = ((size_t)(b0i * NH + h) * NT + t0) * ND;
                size_t base1 = ((size_t)(b1i * NH + h) * NT + t1) * ND;
                *(float2*)&outp[base0 + d] = make_float2(__uint_as_float(f2tf(v00)),
                                                         __uint_as_float(f2tf(v01)));
                *(float2*)&outp[base1 + d] = make_float2(__uint_as_float(f2tf(v10)),
                                                         __uint_as_float(f2tf(v11)));
            }
        }
    }
}

// ---------------------------------------------------------------------------
// Flash attention, static shift, per-head band [0, kmax_h).
// Q tile held in REGISTERS (staged through the Ps buffer once) -> smem 69.0KB
// -> 3 CTAs/SM. Grid (NT/128, NH, NB), 256 threads.
// ---------------------------------------------------------------------------
struct __align__(16) FlashSmem {
    unsigned Ks[2][64][36];     // 18,432 B
    unsigned Vt[2][32][68];     // 17,408 B
    unsigned Ps[128][68];       // 34,816 B (also Q staging area, cols 0..31)
};

__global__ __launch_bounds__(256,3) void flash_attn() {
    extern __shared__ char smraw[];
    FlashSmem& sm = *reinterpret_cast<FlashSmem*>(smraw);
    int q0 = blockIdx.x * 128, h = blockIdx.y, b = blockIdx.z;
    int bh = b * NH + h;
    int kmaxh = kmax_h(h);
    int tid = threadIdx.x, wid = tid >> 5, lane = tid & 31, g = lane >> 2, t = lane & 3;
    int wm = wid * 16;
    int lrow = lane & 15, lcol = 4 * (lane >> 4);
    const float* qp = g_q + (size_t)bh * NT * ND;
    const float* kp = g_k + (size_t)bh * NT * ND;
    const float* vp = g_v + (size_t)bh * ND * NT;

    // Stage Q into Ps (cols 0..31) + K0/V0, one commit group.
#pragma unroll
    for (int i = 0; i < 4; i++) {
        int idx = tid + i * 256; int r = idx >> 3, c = (idx & 7) * 4;
        cpa16(&sm.Ps[r][c], &qp[(size_t)(q0 + r) * ND + c]);
    }
#pragma unroll
    for (int i = 0; i < 2; i++) {
        int idx = tid + i * 256;
        { int r = idx >> 3, c = (idx & 7) * 4;
          cpa16(&sm.Ks[0][r][c], &kp[(size_t)r * ND + c]); }
        { int r = idx >> 4, c = (idx & 15) * 4;
          cpa16(&sm.Vt[0][r][c], &vp[(size_t)r * NT + c]); }
    }
    cpcommit();
    cpwait<0>();
    __syncthreads();

    // Q fragments -> registers (loop-invariant).
    unsigned qa[4][4];
#pragma unroll
    for (int kkq = 0; kkq < 4; kkq++)
        ldsm4(qa[kkq], &sm.Ps[wm + lrow][kkq * 8 + lcol]);

    float slope2 = exp2f(-(float)(h + 1) * (1.0f / 16.0f)) * LOG2E;
    float l0 = 0.f, l1 = 0.f;
    float oacc[4][4] = {};
    int qi0 = q0 + wm + g, qi1 = qi0 + 8;
    float t2f = (float)(2 * t);
    int cb = 0;

    for (int kt = 0; kt < kmaxh; kt += 64, cb ^= 1) {
        __syncthreads();    // Q-staging reads done / prev-iter Ps reads done
        if (kt + 64 < kmaxh) {
            const float* kp2 = kp + (size_t)(kt + 64) * ND;
            const float* vp2 = vp + (kt + 64);
#pragma unroll
            for (int i = 0; i < 2; i++) {
                int idx = tid + i * 256;
                { int r = idx >> 3, c = (idx & 7) * 4;
                  cpa16(&sm.Ks[cb^1][r][c], &kp2[(size_t)r * ND + c]); }
                { int r = idx >> 4, c = (idx & 15) * 4;
                  cpa16(&sm.Vt[cb^1][r][c], &vp2[(size_t)r * NT + c]); }
            }
            cpcommit(); cpwait<1>();
        } else cpwait<0>();
        __syncthreads();

        float sacc[8][4] = {};
#pragma unroll
        for (int kk = 0; kk < 32; kk += 8) {
#pragma unroll
            for (int nj = 0; nj < 8; nj += 2) {
                unsigned r[4];
                ldsm4(r, &sm.Ks[cb][nj * 8 + lrow][kk + lcol]);
                unsigned b0[2] = { r[0], r[2] }, b1[2] = { r[1], r[3] };
                mma8(sacc[nj], qa[kk >> 3], b0); mma8(sacc[nj+1], qa[kk >> 3], b1);
            }
        }
        float base = -slope2 * (float)kt;
#pragma unroll
        for (int ni = 0; ni < 8; ni++) {
            float c0 = base - slope2 * ((float)(ni * 8) + t2f);
            float c1 = c0 - slope2;
            float p0 = ex2f(sacc[ni][0] + c0);
            float p1 = ex2f(sacc[ni][1] + c1);
            float p2 = ex2f(sacc[ni][2] + c0);
            float p3 = ex2f(sacc[ni][3] + c1);
            l0 += p0 + p1; l1 += p2 + p3;
            int col = ni * 8 + 2 * t;
            *(uint2*)&sm.Ps[wm + g][col]     = make_uint2(f2tf(p0), f2tf(p1));
            *(uint2*)&sm.Ps[wm + g + 8][col] = make_uint2(f2tf(p2), f2tf(p3));
        }
        __syncwarp();
#pragma unroll
        for (int kk = 0; kk < 64; kk += 8) {
            unsigned a[4];
            ldsm4(a, &sm.Ps[wm + lrow][kk + lcol]);
#pragma unroll
            for (int nj = 0; nj < 4; nj += 2) {
                unsigned r[4];
                ldsm4(r, &sm.Vt[cb][nj * 8 + lrow][kk + lcol]);
                unsigned b0[2] = { r[0], r[2] }, b1[2] = { r[1], r[3] };
                mma8(oacc[nj], a, b0); mma8(oacc[nj+1], a, b1);
            }
        }
    }
    l0 += __shfl_xor_sync(~0u, l0, 1); l0 += __shfl_xor_sync(~0u, l0, 2);
    l1 += __shfl_xor_sync(~0u, l1, 1); l1 += __shfl_xor_sync(~0u, l1, 2);
    float il0 = __fdividef(1.f, l0), il1 = __fdividef(1.f, l1);
#pragma unroll
    for (int ni = 0; ni < 4; ni++) {
        int col = ni * 8 + 2 * t;
        *(float2*)&g_o[((size_t)bh * NT + qi0) * ND + col] =
            make_float2(__uint_as_float(f2tf(oacc[ni][0] * il0)),
                        __uint_as_float(f2tf(oacc[ni][1] * il0)));
        *(float2*)&g_o[((size_t)bh * NT + qi1) * ND + col] =
            make_float2(__uint_as_float(f2tf(oacc[ni][2] * il1)),
                        __uint_as_float(f2tf(oacc[ni][3] * il1)));
    }
    if (t == 0) {
        g_ms[(size_t)bh * NT + qi0] = lg2f(l0);
        g_ms[(size_t)bh * NT + qi1] = lg2f(l1);
    }
}

// ---------------------------------------------------------------------------
// Fused tail, COMPACT grid (32, 16): by<8 -> gemm_out, by>=8 -> in-band avg.
// Out-of-band avg zero-filled by gemm_qkv. 256 threads, dyn smem 55,296 B.
// ---------------------------------------------------------------------------
__global__ __launch_bounds__(256,3) void fused_tail(const float* __restrict__ bo,
                                                    float* __restrict__ out,
                                                    float* __restrict__ avg) {
    extern __shared__ char smraw[];
    int tid = threadIdx.x;

    if (blockIdx.y < 8) {
        // ---------------- gemm_out ----------------
        GemmSmem& sm = *reinterpret_cast<GemmSmem*>(smraw);
        const float* Wo = g_wr[3];
        int m0 = blockIdx.x * 128, n0 = blockIdx.y * 64;
        int wid = tid >> 5, lane = tid & 31, g = lane >> 2, t = lane & 3;
        int wm = (wid & 3) * 32, wn = (wid >> 2) * 32;
        int lrow = lane & 15, lcol = 4 * (lane >> 4);

        {
#pragma unroll
            for (int i = 0; i < 4; i++) {
                int idx = tid + i * 256; int r = idx >> 3, c = (idx & 7) * 4;
                int m = m0 + r; int bi = m >> 11, tt = m & 2047;
                cpa16(&sm.As[0][r][c], &g_o[((size_t)(bi * NH) * NT + tt) * ND + c]);
            }
#pragma unroll
            for (int i = 0; i < 2; i++) {
                int idx = tid + i * 256; int r = idx >> 3, c = (idx & 7) * 4;
                cpa16(&sm.Bs[0][r][c], &Wo[(size_t)(n0 + r) * NC + c]);
            }
            cpcommit();
        }

        float acc[2][4][4] = {};
        int cb = 0;
        for (int k0 = 0; k0 < NC; k0 += 32, cb ^= 1) {
            __syncthreads();
            if (k0 + 32 < NC) {
                int kn = k0 + 32;
                int hh = kn >> 5;
#pragma unroll
                for (int i = 0; i < 4; i++) {
                    int idx = tid + i * 256; int r = idx >> 3, c = (idx & 7) * 4;
                    int m = m0 + r; int bi = m >> 11, tt = m & 2047;
                    cpa16(&sm.As[cb^1][r][c], &g_o[((size_t)(bi * NH + hh) * NT + tt) * ND + c]);
                }
#pragma unroll
                for (int i = 0; i < 2; i++) {
                    int idx = tid + i * 256; int r = idx >> 3, c = (idx & 7) * 4;
                    cpa16(&sm.Bs[cb^1][r][c], &Wo[(size_t)(n0 + r) * NC + kn + c]);
                }
                cpcommit(); cpwait<1>();
            } else cpwait<0>();
            __syncthreads();
#pragma unroll
            for (int kk = 0; kk < 32; kk += 8) {
                unsigned a[2][4];
                ldsm4(a[0], &sm.As[cb][wm + lrow][kk + lcol]);
                ldsm4(a[1], &sm.As[cb][wm + 16 + lrow][kk + lcol]);
#pragma unroll
                for (int nj = 0; nj < 4; nj += 2) {
                    unsigned r[4];
                    ldsm4(r, &sm.Bs[cb][wn + nj * 8 + lrow][kk + lcol]);
                    unsigned b0[2] = { r[0], r[2] }, b1[2] = { r[1], r[3] };
                    mma8(acc[0][nj], a[0], b0);  mma8(acc[0][nj+1], a[0], b1);
                    mma8(acc[1][nj], a[1], b0);  mma8(acc[1][nj+1], a[1], b1);
                }
            }
        }
#pragma unroll
        for (int mi = 0; mi < 2; mi++) {
            int r0 = m0 + wm + mi * 16 + g;
            int r1 = r0 + 8;
#pragma unroll
            for (int ni = 0; ni < 4; ni++) {
                int n = n0 + wn + ni * 8 + 2 * t;
                float bb0 = bo[n], bb1 = bo[n + 1];
                *(float2*)&out[(size_t)r0 * NC + n] = make_float2(acc[mi][ni][0] + bb0, acc[mi][ni][1] + bb1);
                *(float2*)&out[(size_t)r1 * NC + n] = make_float2(acc[mi][ni][2] + bb0, acc[mi][ni][3] + bb1);
            }
        }
        return;
    }

    // ---------------- avg_probs (in-band only) ----------------
    int j = blockIdx.x + 32 * (blockIdx.y - 8);    // 0..255
    int b = j >> 7;
    int r7 = j & 127;
    int q0 = (r7 >> 2) * 64;
    int k0 = (r7 & 3) * 64;

    // first head whose band covers this k-tile (earlier heads give exact 0)
    int h0 = (k0 >= 192) ? 13 : (k0 >= 128) ? 4 : 0;

    AvgSmem& sma = *reinterpret_cast<AvgSmem*>(smraw);
    int wid = tid >> 5, lane = tid & 31, g = lane >> 2, t = lane & 3;
    int wm = (wid >> 1) * 16, wn = (wid & 1) * 32;
    int lrow = lane & 15, lcol = 4 * (lane >> 4);
    int qi0 = q0 + wm + g, qi1 = qi0 + 8;
    float kj0f = (float)(k0 + wn + 2 * t);

    {
        int bh = b * NH + h0;
#pragma unroll
        for (int i = 0; i < 2; i++) {
            int idx = tid + i * 256; int r = idx >> 3, c = (idx & 7) * 4;
            cpa16(&sma.Qs[0][r][c], &g_q[((size_t)bh * NT + q0 + r) * ND + c]);
            cpa16(&sma.Ks[0][r][c], &g_k[((size_t)bh * NT + k0 + r) * ND + c]);
        }
        cpcommit();
    }
    float acc[4][4] = {};
    int cb = 0;
    for (int h = h0; h < NH; h++, cb ^= 1) {
        int bh = b * NH + h;
        __syncthreads();
        if (h + 1 < NH) {
            int bh2 = bh + 1;
#pragma unroll
            for (int i = 0; i < 2; i++) {
                int idx = tid + i * 256; int r = idx >> 3, c = (idx & 7) * 4;
                cpa16(&sma.Qs[cb^1][r][c], &g_q[((size_t)bh2 * NT + q0 + r) * ND + c]);
                cpa16(&sma.Ks[cb^1][r][c], &g_k[((size_t)bh2 * NT + k0 + r) * ND + c]);
            }
            cpcommit(); cpwait<1>();
        } else cpwait<0>();
        __syncthreads();

        float sacc[4][4] = {};
#pragma unroll
        for (int kk = 0; kk < 32; kk += 8) {
            unsigned a[4];
            ldsm4(a, &sma.Qs[cb][wm + lrow][kk + lcol]);
#pragma unroll
            for (int nj = 0; nj < 4; nj += 2) {
                unsigned r[4];
                ldsm4(r, &sma.Ks[cb][wn + nj * 8 + lrow][kk + lcol]);
                unsigned b0[2] = { r[0], r[2] }, b1[2] = { r[1], r[3] };
                mma8(sacc[nj], a, b0); mma8(sacc[nj+1], a, b1);
            }
        }
        float M0 = g_ms[(size_t)bh * NT + qi0];
        float M1 = g_ms[(size_t)bh * NT + qi1];
        float slope2 = exp2f(-(float)(h + 1) * (1.0f / 16.0f)) * LOG2E;
        float c0 = fmaf(-slope2, kj0f, -M0);
        float c1 = fmaf(-slope2, kj0f, -M1);
#pragma unroll
        for (int ni = 0; ni < 4; ni++) {
            float d0 = c0 - slope2 * (float)(ni * 8);
            float d1 = c1 - slope2 * (float)(ni * 8);
            acc[ni][0] += ex2f(sacc[ni][0] + d0);
            acc[ni][1] += ex2f(sacc[ni][1] + d0 - slope2);
            acc[ni][2] += ex2f(sacc[ni][2] + d1);
            acc[ni][3] += ex2f(sacc[ni][3] + d1 - slope2);
        }
    }
#pragma unroll
    for (int ni = 0; ni < 4; ni++) {
        int col = k0 + wn + ni * 8 + 2 * t;
        *(float2*)&avg[((size_t)b * NT + qi0) * NT + col] =
            make_float2(acc[ni][0] * 0.0625f, acc[ni][1] * 0.0625f);
        *(float2*)&avg[((size_t)b * NT + qi1) * NT + col] =
            make_float2(acc[ni][2] * 0.0625f, acc[ni][3] * 0.0625f);
    }
}

// ---------------------------------------------------------------------------
extern "C" void kernel_launch(void* const* d_in, const int* in_sizes, int n_in,
                              void* d_out, int out_size) {
    const float* x  = (const float*)d_in[0];
    const float* Wq = (const float*)d_in[1];
    const float* bq = (const float*)d_in[2];
    const float* Wk = (const float*)d_in[3];
    const float* bk = (const float*)d_in[4];
    const float* Wv = (const float*)d_in[5];
    const float* bv = (const float*)d_in[6];
    const float* Wo = (const float*)d_in[7];
    const float* bo = (const float*)d_in[8];

    float* out = (float*)d_out;                 // (B,T,C)
    float* avg = out + (size_t)NB*NT*NC;        // (B,T,T)

    cudaFuncSetAttribute(gemm_qkv, cudaFuncAttributeMaxDynamicSharedMemorySize,
                         (int)sizeof(GemmSmem));
    cudaFuncSetAttribute(flash_attn, cudaFuncAttributeMaxDynamicSharedMemorySize,
                         (int)sizeof(FlashSmem));
    cudaFuncSetAttribute(fused_tail, cudaFuncAttributeMaxDynamicSharedMemorySize,
                         (int)sizeof(GemmSmem));

    int npre = (BT * NC / 4 + 4 * NC * NC / 4) / 256;
    pre_round<<<npre, 256>>>(x, Wq, Wk, Wv, Wo);

    dim3 g1(BT/128, NC/64, 3);
    gemm_qkv<<<g1, 256, sizeof(GemmSmem)>>>(bq, bk, bv, avg);

    dim3 g2(NT/128, NH, NB);
    flash_attn<<<g2, 256, sizeof(FlashSmem)>>>();

    dim3 g3(32, 16);
    fused_tail<<<g3, 256, sizeof(GemmSmem)>>>(bo, out, avg);
}